// round 17
// baseline (speedup 1.0000x reference)
#include <cuda_runtime.h>
#include <cstdint>

#define D    128
#define OUTC 16
#define MAXN 50000

typedef unsigned long long ull;

__device__ float    g_P[MAXN * 32];  // [n][0:16]=W_u.hn + b, [n][16:32]=W_v.hn
__device__ unsigned g_ctr;           // monotonic grid-barrier counter (replay-safe)

__device__ __forceinline__ ull pack2(float v) {
    ull r;
    asm("mov.b64 %0, {%1, %1};" : "=l"(r) : "r"(__float_as_uint(v)));
    return r;
}
__device__ __forceinline__ ull f2fma(ull a, ull b, ull c) {
    ull d;
    asm("fma.rn.f32x2 %0, %1, %2, %3;" : "=l"(d) : "l"(a), "l"(b), "l"(c));
    return d;
}
__device__ __forceinline__ unsigned smem_u32(const void* p) {
    return (unsigned)__cvta_generic_to_shared(p);
}
__device__ __forceinline__ void cp16(unsigned s, const void* g) {
    asm volatile("cp.async.cg.shared.global [%0], [%1], 16;" :: "r"(s), "l"(g));
}
__device__ __forceinline__ void cp_commit() {
    asm volatile("cp.async.commit_group;");
}
template <int N>
__device__ __forceinline__ void cp_wait() {
    asm volatile("cp.async.wait_group %0;" :: "n"(N));
}

// ===========================================================================
// Fused persistent kernel, grid 296, 2 CTAs/SM.
// Part 1: node projection in 64-NODE tiles (782 tiles, 2-3/CTA -> balanced
// critical path ~15us, hidden under the edge GEMM prologue ~22us).
// Grid barrier via monotonic counter. Part 2: proven edge core (512-edge
// subtiles, 8 phases of 16 k, depth-2 cp.async, 4 edges/thread); warps wait
// for the barrier only at their FIRST P-gather epilogue.
// ===========================================================================
__global__ __launch_bounds__(256, 2) void fused_kernel(
        const float* __restrict__ hn,
        const float* __restrict__ he,
        const unsigned* __restrict__ srcw,
        const unsigned* __restrict__ dstw,
        const float* __restrict__ W,
        const float* __restrict__ b,
        float* __restrict__ out, int N, int E) {
    extern __shared__ float sm[];
    __shared__ unsigned s_nonzero;
    __shared__ unsigned s_target;

    int tid  = threadIdx.x;
    int bid  = blockIdx.x;
    int grid = gridDim.x;

    if (tid == 0) s_nonzero = 0u;

    // ---- CTA-local index dtype probe (int64 -> odd words all zero) ----
    if (tid < 64) {
        unsigned v = (tid < 32) ? srcw[2 * tid + 1] : dstw[2 * (tid - 32) + 1];
        if (v) atomicOr(&s_nonzero, 1u);
    }

    // ================= Part 1: node projection (64-node tiles) =============
    {
        float* buf0 = sm;                        // [64 rows][36]
        float* buf1 = sm + 64 * 36;
        ull*   Wp   = (ull*)(sm + 2 * 64 * 36);  // [128 k][16 pairs]

        int srow = tid >> 3, scol = tid & 7;     // rows srow, srow+32
        int q    = tid & 3;                      // output quarter (pairs q*4..q*4+3)
        int g    = tid >> 2;                     // node 0..63

        int ntiles = (N + 63) >> 6;
        bool first = true;

        for (int t = bid; t < ntiles; t += grid) {
            int n0 = t << 6;

            auto stage = [&](int p) {
                float* buf = (p & 1) ? buf1 : buf0;
                int ph = p & 3;
#pragma unroll
                for (int tt = 0; tt < 2; tt++) {
                    int r = srow + tt * 32;
                    int rg = n0 + r; if (rg >= N) rg = N - 1;
                    cp16(smem_u32(buf + r * 36 + scol * 4),
                         hn + (size_t)rg * D + ph * 32 + scol * 4);
                }
                cp_commit();
            };

            stage(0);
            stage(1);

            if (first) {
                for (int i = tid; i < 128 * 16; i += 256) {
                    int k = i >> 4, pg = i & 15;
                    float w0, w1;
                    if (pg < 8) { w0 = W[(2 * pg) * 384 + k];            w1 = W[(2 * pg + 1) * 384 + k]; }
                    else        { w0 = W[(2 * pg - 16) * 384 + 128 + k]; w1 = W[(2 * pg - 15) * 384 + 128 + k]; }
                    float2 tt = make_float2(w0, w1);
                    Wp[i] = *(ull*)&tt;
                }
                first = false;
            }

            ull acc[4];
#pragma unroll
            for (int pp = 0; pp < 4; pp++) acc[pp] = 0ull;

#pragma unroll 1
            for (int p = 0; p < 4; p++) {
                if (p == 3) cp_wait<0>(); else cp_wait<1>();
                __syncthreads();
                const float* buf = (p & 1) ? buf1 : buf0;
                int k0 = p * 32;
#pragma unroll
                for (int kc = 0; kc < 8; kc++) {
                    float4 h0 = *(const float4*)(buf + g * 36 + kc * 4);
                    float hv0[4] = {h0.x, h0.y, h0.z, h0.w};
#pragma unroll
                    for (int kk = 0; kk < 4; kk++) {
                        const ull* wr = Wp + (size_t)(k0 + kc * 4 + kk) * 16 + q * 4;
                        ulonglong2 a  = *(const ulonglong2*)wr;
                        ulonglong2 bq = *(const ulonglong2*)(wr + 2);
                        ull hA = pack2(hv0[kk]);
                        acc[0] = f2fma(hA, a.x,  acc[0]);
                        acc[1] = f2fma(hA, a.y,  acc[1]);
                        acc[2] = f2fma(hA, bq.x, acc[2]);
                        acc[3] = f2fma(hA, bq.y, acc[3]);
                    }
                }
                __syncthreads();
                if (p < 2) stage(p + 2);
            }

            if (q < 2) {
#pragma unroll
                for (int pp = 0; pp < 4; pp++) {
                    float2 bb = *(const float2*)(b + 2 * (q * 4 + pp));
                    float2 a = *(float2*)&acc[pp];
                    a.x += bb.x; a.y += bb.y;
                    acc[pp] = *(ull*)&a;
                }
            }

            int n = n0 + g;
            if (n < N) {
                ull* po = (ull*)(g_P + (size_t)n * 32 + q * 8);
#pragma unroll
                for (int pp = 0; pp < 4; pp++) po[pp] = acc[pp];
            }
        }
    }

    // ---- arrive on grid barrier (release P writes) ----
    __threadfence();
    __syncthreads();
    if (tid == 0) {
        unsigned ticket = atomicAdd(&g_ctr, 1u);
        s_target = (ticket / (unsigned)grid + 1u) * (unsigned)grid;
    }
    __syncthreads();                     // node smem free for edge reuse
    unsigned target = s_target;
    int stride = s_nonzero ? 1 : 2;

    // ========================= Part 2: edge pass ==========================
    {
        float* buf0 = sm;                        // [512 rows][20]
        float* buf1 = sm + 512 * 20;
        ull*   Wp   = (ull*)(sm + 2 * 512 * 20); // [128 k][8 pairs]

        int srow = tid >> 2, scol = tid & 3;
        int half = tid & 1;
        int g    = tid >> 1;

        int nsub = (E + 511) >> 9;
        int nw   = (bid < nsub) ? ((nsub - bid + grid - 1) / grid) : 0;
        int nph  = nw * 8;
        if (nph == 0) return;

        auto stage = [&](int p) {
            int w = p >> 3, ph = p & 7;
            int eb = (bid + w * grid) << 9;
            float* buf = (p & 1) ? buf1 : buf0;
#pragma unroll
            for (int t = 0; t < 8; t++) {
                int r = srow + t * 64;
                int rg = eb + r; if (rg >= E) rg = E - 1;
                cp16(smem_u32(buf + r * 20 + scol * 4),
                     he + (size_t)rg * D + ph * 16 + scol * 4);
            }
            cp_commit();
        };

        stage(0);
        stage(1);

        for (int i = tid; i < 128 * 8; i += 256) {
            int k = i >> 3, pg = i & 7;
            float2 t = make_float2(W[(2 * pg) * 384 + 256 + k],
                                   W[(2 * pg + 1) * 384 + 256 + k]);
            Wp[i] = *(ull*)&t;
        }

        ull acc[4][4];
#pragma unroll
        for (int j = 0; j < 4; j++)
#pragma unroll
            for (int pp = 0; pp < 4; pp++) acc[j][pp] = 0ull;

        int sidx[4], didx[4];
        bool p_ready = false;

#pragma unroll 1
        for (int p = 0; p < nph; p++) {
            int ph = p & 7, w = p >> 3;
            int eb = (bid + w * grid) << 9;

            if (ph == 0) {
#pragma unroll
                for (int j = 0; j < 4; j++) {
                    int e = eb + g + 128 * j; if (e >= E) e = E - 1;
                    sidx[j] = (int)srcw[(size_t)e * stride];
                    didx[j] = (int)dstw[(size_t)e * stride];
                }
            }

            if (p == nph - 1) cp_wait<0>(); else cp_wait<1>();
            __syncthreads();

            const float* buf = (p & 1) ? buf1 : buf0;
            int k0 = ph * 16;
#pragma unroll
            for (int kc = 0; kc < 4; kc++) {
                float4 h0 = *(const float4*)(buf + (g      ) * 20 + kc * 4);
                float4 h1 = *(const float4*)(buf + (g + 128) * 20 + kc * 4);
                float4 h2 = *(const float4*)(buf + (g + 256) * 20 + kc * 4);
                float4 h3 = *(const float4*)(buf + (g + 384) * 20 + kc * 4);
                float hv0[4] = {h0.x, h0.y, h0.z, h0.w};
                float hv1[4] = {h1.x, h1.y, h1.z, h1.w};
                float hv2[4] = {h2.x, h2.y, h2.z, h2.w};
                float hv3[4] = {h3.x, h3.y, h3.z, h3.w};
#pragma unroll
                for (int kk = 0; kk < 4; kk++) {
                    const ull* wr = Wp + (size_t)(k0 + kc * 4 + kk) * 8 + half * 4;
                    ulonglong2 a  = *(const ulonglong2*)wr;
                    ulonglong2 bq = *(const ulonglong2*)(wr + 2);
                    ull w0 = a.x, w1 = a.y, w2 = bq.x, w3 = bq.y;
                    ull hA = pack2(hv0[kk]);
                    ull hB = pack2(hv1[kk]);
                    ull hC = pack2(hv2[kk]);
                    ull hD = pack2(hv3[kk]);
                    acc[0][0] = f2fma(hA, w0, acc[0][0]);
                    acc[0][1] = f2fma(hA, w1, acc[0][1]);
                    acc[0][2] = f2fma(hA, w2, acc[0][2]);
                    acc[0][3] = f2fma(hA, w3, acc[0][3]);
                    acc[1][0] = f2fma(hB, w0, acc[1][0]);
                    acc[1][1] = f2fma(hB, w1, acc[1][1]);
                    acc[1][2] = f2fma(hB, w2, acc[1][2]);
                    acc[1][3] = f2fma(hB, w3, acc[1][3]);
                    acc[2][0] = f2fma(hC, w0, acc[2][0]);
                    acc[2][1] = f2fma(hC, w1, acc[2][1]);
                    acc[2][2] = f2fma(hC, w2, acc[2][2]);
                    acc[2][3] = f2fma(hC, w3, acc[2][3]);
                    acc[3][0] = f2fma(hD, w0, acc[3][0]);
                    acc[3][1] = f2fma(hD, w1, acc[3][1]);
                    acc[3][2] = f2fma(hD, w2, acc[3][2]);
                    acc[3][3] = f2fma(hD, w3, acc[3][3]);
                }
            }
            __syncthreads();

            if (p + 2 < nph) stage(p + 2);

            if (ph == 7) {
                if (!p_ready) {
                    if ((tid & 31) == 0) {
                        while (atomicAdd(&g_ctr, 0u) < target) __nanosleep(128);
                    }
                    __syncwarp();
                    __threadfence();     // invalidate L1D so P reads are fresh
                    p_ready = true;
                }
#pragma unroll
                for (int j = 0; j < 4; j++) {
                    int e = eb + g + 128 * j;
                    if (e >= E) continue;
                    const float4* pu = (const float4*)(g_P + (size_t)sidx[j] * 32 + half * 8);
                    const float4* pv = (const float4*)(g_P + (size_t)didx[j] * 32 + 16 + half * 8);
                    float4 u0 = pu[0], u1 = pu[1];
                    float4 v0 = pv[0], v1 = pv[1];
                    float2 a0 = *(float2*)&acc[j][0];
                    float2 a1 = *(float2*)&acc[j][1];
                    float2 a2 = *(float2*)&acc[j][2];
                    float2 a3 = *(float2*)&acc[j][3];
                    float4 r0, r1;
                    r0.x = a0.x + u0.x + v0.x;
                    r0.y = a0.y + u0.y + v0.y;
                    r0.z = a1.x + u0.z + v0.z;
                    r0.w = a1.y + u0.w + v0.w;
                    r1.x = a2.x + u1.x + v1.x;
                    r1.y = a2.y + u1.y + v1.y;
                    r1.z = a3.x + u1.z + v1.z;
                    r1.w = a3.y + u1.w + v1.w;
                    float4* op = (float4*)(out + (size_t)e * OUTC + half * 8);
                    op[0] = r0;
                    op[1] = r1;
                }
#pragma unroll
                for (int j = 0; j < 4; j++)
#pragma unroll
                    for (int pp = 0; pp < 4; pp++) acc[j][pp] = 0ull;
            }
        }
    }
}

// ===========================================================================
extern "C" void kernel_launch(void* const* d_in, const int* in_sizes, int n_in,
                              void* d_out, int out_size) {
    const float*    hn   = (const float*)d_in[0];
    const float*    he   = (const float*)d_in[1];
    const unsigned* srcw = (const unsigned*)d_in[2];
    const unsigned* dstw = (const unsigned*)d_in[3];
    const float*    W    = (const float*)d_in[4];
    const float*    b    = (const float*)d_in[5];
    float*          out  = (float*)d_out;

    int N = in_sizes[0] / D;
    int E = in_sizes[1] / D;

    const int smem = 2 * 512 * 20 * 4 + 128 * 8 * 8;   // 90112 B (edge layout, superset)
    cudaFuncSetAttribute(fused_kernel,
                         cudaFuncAttributeMaxDynamicSharedMemorySize, smem);

    fused_kernel<<<296, 256, smem>>>(hn, he, srcw, dstw, W, b, out, N, E);
}